// round 14
// baseline (speedup 1.0000x reference)
#include <cuda_runtime.h>
#include <cuda_fp16.h>
#include <cstdint>

#define N_B    131072
#define D_IN   128
#define D_OUT  512
#define VBS    128
#define EPS_BN 1e-5f

// ---------------- SMEM layout (bytes) ----------------
#define SA      0           // A tile 32KB (128x128 fp16, 256B row stride, swizzled)
#define SW0     32768       // W tile buffer 0, 32KB
#define SW1     65536       // W tile buffer 1, 32KB
#define SSUM    98304       // 4 (mw) x 512 cols f32 partial sums
#define SSQ     106496      // 4 x 512 f32 partial sumsq
#define SAB_A   114688      // 512 f32 affine scale
#define SAB_B   116736      // 512 f32 affine shift
#define SM_TOT  118784

// W pre-converted to fp16, swizzled, chunk-tiled: 4 chunks x 32KB
__device__ __align__(16) unsigned char gWh[131072];

__device__ __forceinline__ uint32_t smem_u32(const void* p) {
    uint32_t a;
    asm("{ .reg .u64 t; cvta.to.shared.u64 t, %1; cvt.u32.u64 %0, t; }" : "=r"(a) : "l"(p));
    return a;
}
__device__ __forceinline__ void ldsm4(uint32_t* r, uint32_t addr) {
    asm volatile("ldmatrix.sync.aligned.m8n8.x4.shared.b16 {%0,%1,%2,%3}, [%4];"
                 : "=r"(r[0]), "=r"(r[1]), "=r"(r[2]), "=r"(r[3]) : "r"(addr));
}
__device__ __forceinline__ void mma16816(float* c, const uint32_t* a, const uint32_t* b) {
    asm volatile("mma.sync.aligned.m16n8k16.row.col.f32.f16.f16.f32 "
                 "{%0,%1,%2,%3}, {%4,%5,%6,%7}, {%8,%9}, {%0,%1,%2,%3};"
                 : "+f"(c[0]), "+f"(c[1]), "+f"(c[2]), "+f"(c[3])
                 : "r"(a[0]), "r"(a[1]), "r"(a[2]), "r"(a[3]), "r"(b[0]), "r"(b[1]));
}
__device__ __forceinline__ uint32_t pkh(float a, float b) {
    __half2 h = __floats2half2_rn(a, b);
    union { __half2 v; uint32_t u; } cv; cv.v = h;
    return cv.u;
}
__device__ __forceinline__ void cp16(uint32_t saddr, const void* g) {
    asm volatile("cp.async.cg.shared.global [%0], [%1], 16;" :: "r"(saddr), "l"(g) : "memory");
}
__device__ __forceinline__ void cp_commit() {
    asm volatile("cp.async.commit_group;" ::: "memory");
}

// ============================================================================
// Prep: W [512,128] f32 -> fp16, swizzled, chunk-tiled in gWh (once/launch).
// ============================================================================
__global__ __launch_bounds__(256) void prep_w(const float* __restrict__ W) {
    int idx = blockIdx.x * 256 + threadIdx.x;    // 0..8191 (16B chunks)
    int c = idx >> 11, j = idx & 2047;
    int row = j >> 4, ch = j & 15;
    const float4* gp = reinterpret_cast<const float4*>(W + ((size_t)(c * 128 + row) * 128 + ch * 8));
    float4 u = gp[0], v = gp[1];
    uint4 h4 = make_uint4(pkh(u.x, u.y), pkh(u.z, u.w),
                          pkh(v.x, v.y), pkh(v.z, v.w));
    *reinterpret_cast<uint4*>(gWh + c * 32768 + row * 256 + ((ch ^ (row & 7)) << 4)) = h4;
}

// ============================================================================
// Fused: fp16 mma GEMM (raw x -> out, L2-resident round trip, exact f32) +
// deferred GhostBN fold + sparsemax tail (4-row interleaved Newton) applying
// (x*a+b)*prior in-register.
// grid = 1024 (one CTA per virtual batch of 128 rows), block = 512.
// ============================================================================
__global__ __launch_bounds__(512, 1) void fused_attentive(
    float* __restrict__ out, const float* __restrict__ priors,
    const float* __restrict__ feat,
    const float* __restrict__ gamma, const float* __restrict__ beta)
{
    extern __shared__ char smem[];
    const uint32_t sb = smem_u32(smem);
    const int tid = threadIdx.x;
    const int w = tid >> 5, lane = tid & 31;
    const int mw = w & 3, nw = w >> 2;           // warp grid 4(M) x 4(N)
    const int m0 = blockIdx.x * VBS;

    float* ssum = reinterpret_cast<float*>(smem + SSUM);
    float* ssq  = reinterpret_cast<float*>(smem + SSQ);
    float* aarr = reinterpret_cast<float*>(smem + SAB_A);
    float* barr = reinterpret_cast<float*>(smem + SAB_B);

    // ---- prefetch W chunks 0,1 via cp.async (pre-swizzled fp16: linear copy) ----
    #pragma unroll
    for (int i = 0; i < 4; i++) {
        int idx = tid + i * 512;
        cp16(sb + SW0 + idx * 16, gWh + idx * 16);
    }
    cp_commit();
    #pragma unroll
    for (int i = 0; i < 4; i++) {
        int idx = tid + i * 512;
        cp16(sb + SW1 + idx * 16, gWh + 32768 + idx * 16);
    }
    cp_commit();

    // ---- A tile (feat 128x128) — conversion overlaps W cp.async ----
    {
        const float* g = feat + (size_t)m0 * D_IN;
        #pragma unroll
        for (int i = 0; i < 4; i++) {
            int idx = tid + i * 512;             // 2048 16B chunk-slots
            int row = idx >> 4, ch = idx & 15;
            const float4* gp = reinterpret_cast<const float4*>(g + row * 128 + ch * 8);
            float4 u = gp[0], v = gp[1];
            uint4 h4 = make_uint4(pkh(u.x, u.y), pkh(u.z, u.w),
                                  pkh(v.x, v.y), pkh(v.z, v.w));
            uint32_t off = (uint32_t)(row * 256 + ((ch ^ (row & 7)) << 4));
            *reinterpret_cast<uint4*>(smem + SA + off) = h4;
        }
    }

    // per-lane ldmatrix address components
    const int a_row = mw * 32 + (((lane >> 3) & 1) << 3) + (lane & 7);
    const int a_sel = lane >> 4;
    const int b_row = nw * 32 + ((lane >> 4) << 3) + (lane & 7);
    const int b_sel = (lane >> 3) & 1;
    const int a_m7 = a_row & 7, b_m7 = b_row & 7;

    #pragma unroll 1
    for (int chunk = 0; chunk < 4; chunk++) {
        if (chunk < 3) asm volatile("cp.async.wait_group 1;" ::: "memory");
        else           asm volatile("cp.async.wait_group 0;" ::: "memory");
        __syncthreads();
        const uint32_t swb = (chunk & 1) ? (sb + SW1) : (sb + SW0);

        // ---- GEMM: warp tile 32(M) x 32(N) ----
        float acc[2][4][4];
        #pragma unroll
        for (int mt = 0; mt < 2; mt++)
            #pragma unroll
            for (int nt = 0; nt < 4; nt++)
                #pragma unroll
                for (int q = 0; q < 4; q++) acc[mt][nt][q] = 0.0f;

        #pragma unroll
        for (int s = 0; s < 8; s++) {
            uint32_t aF[2][4], bF[2][4];
            #pragma unroll
            for (int mt = 0; mt < 2; mt++) {
                uint32_t off = (uint32_t)((a_row + mt * 16) * 256 +
                               (((2 * s + a_sel) ^ a_m7) << 4));
                ldsm4(aF[mt], sb + SA + off);
            }
            #pragma unroll
            for (int np = 0; np < 2; np++) {
                uint32_t off = (uint32_t)((b_row + np * 16) * 256 +
                               (((2 * s + b_sel) ^ b_m7) << 4));
                ldsm4(bF[np], swb + off);
            }
            #pragma unroll
            for (int mt = 0; mt < 2; mt++)
                #pragma unroll
                for (int nt = 0; nt < 4; nt++)
                    mma16816(acc[mt][nt], aF[mt], &bF[nt >> 1][(nt & 1) * 2]);
        }

        // ---- store raw x to out (L2-resident round trip, exact f32) ----
        #pragma unroll
        for (int nt = 0; nt < 4; nt++) {
            int gcol = chunk * 128 + nw * 32 + nt * 8 + 2 * (lane & 3);
            #pragma unroll
            for (int mt = 0; mt < 2; mt++) {
                int r0 = m0 + mw * 32 + mt * 16 + (lane >> 2);
                *reinterpret_cast<float2*>(out + (size_t)r0 * D_OUT + gcol) =
                    make_float2(acc[mt][nt][0], acc[mt][nt][1]);
                *reinterpret_cast<float2*>(out + (size_t)(r0 + 8) * D_OUT + gcol) =
                    make_float2(acc[mt][nt][2], acc[mt][nt][3]);
            }
        }

        // ---- column stats (race-free slots: (mw, global col) unique; no sync) ----
        #pragma unroll
        for (int nt = 0; nt < 4; nt++) {
            float s0 = 0.f, s1 = 0.f, q0 = 0.f, q1 = 0.f;
            #pragma unroll
            for (int mt = 0; mt < 2; mt++) {
                float c0 = acc[mt][nt][0], c1 = acc[mt][nt][1];
                float c2 = acc[mt][nt][2], c3 = acc[mt][nt][3];
                s0 += c0 + c2;  s1 += c1 + c3;
                q0 += c0 * c0 + c2 * c2;  q1 += c1 * c1 + c3 * c3;
            }
            #pragma unroll
            for (int o = 4; o < 32; o <<= 1) {
                s0 += __shfl_xor_sync(0xffffffffu, s0, o);
                s1 += __shfl_xor_sync(0xffffffffu, s1, o);
                q0 += __shfl_xor_sync(0xffffffffu, q0, o);
                q1 += __shfl_xor_sync(0xffffffffu, q1, o);
            }
            if (lane < 4) {
                int gcol = chunk * 128 + nw * 32 + nt * 8 + 2 * lane;
                ssum[mw * 512 + gcol]     = s0;  ssum[mw * 512 + gcol + 1] = s1;
                ssq [mw * 512 + gcol]     = q0;  ssq [mw * 512 + gcol + 1] = q1;
            }
        }
        __syncthreads();   // MMA reads of swb done -> safe to prefetch into it

        if (chunk + 2 < 4) {
            const unsigned char* src = gWh + (chunk + 2) * 32768;
            #pragma unroll
            for (int i = 0; i < 4; i++) {
                int idx = tid + i * 512;
                cp16(swb + idx * 16, src + idx * 16);
            }
            cp_commit();
        }
    }

    // ---- fold BN into per-col affine (once, deterministic combine) ----
    {
        int c = tid;                               // 512 threads = 512 cols
        float s = ssum[c] + ssum[512 + c] + ssum[1024 + c] + ssum[1536 + c];
        float q = ssq[c]  + ssq[512 + c]  + ssq[1024 + c]  + ssq[1536 + c];
        float mean = s * (1.0f / VBS);
        float var  = q * (1.0f / VBS) - mean * mean;
        float av = gamma[c] * rsqrtf(var + EPS_BN);
        aarr[c] = av;
        barr[c] = beta[c] - mean * av;
    }
    __syncthreads();

    // ======================= fused sparsemax tail ===========================
    // Warp owns 8 rows, processed as 2 groups of 4 rows with fully interleaved
    // Newton chains (4 independent shfl reductions overlap; support counts via
    // redux.sync). x re-read is an L2 hit; y=(x*a+b)*prior in-register.
    // Monotone Newton from t0=max-1 is the exact fixed point of the
    // piecewise-linear sparsemax equation.
    #pragma unroll 1
    for (int g = 0; g < 2; g++) {
        const int rbase = m0 + w * 8 + g * 4;

        float v[4][16];
        // load + affine + prior (a/b reloaded from SMEM per row: saves regs)
        #pragma unroll
        for (int r = 0; r < 4; r++) {
            const float4* rp = reinterpret_cast<const float4*>(out + (size_t)(rbase + r) * D_OUT);
            const float4* pp = reinterpret_cast<const float4*>(priors + (size_t)(rbase + r) * D_OUT);
            #pragma unroll
            for (int j = 0; j < 4; j++) {
                float4 x  = rp[j * 32 + lane];
                float4 p  = pp[j * 32 + lane];
                float4 a4 = *reinterpret_cast<const float4*>(aarr + j * 128 + lane * 4);
                float4 b4 = *reinterpret_cast<const float4*>(barr + j * 128 + lane * 4);
                v[r][j * 4 + 0] = fmaf(x.x, a4.x, b4.x) * p.x;
                v[r][j * 4 + 1] = fmaf(x.y, a4.y, b4.y) * p.y;
                v[r][j * 4 + 2] = fmaf(x.z, a4.z, b4.z) * p.z;
                v[r][j * 4 + 3] = fmaf(x.w, a4.w, b4.w) * p.w;
            }
        }

        // row maxima (4 interleaved shfl chains)
        float mv[4];
        #pragma unroll
        for (int r = 0; r < 4; r++) {
            float m = v[r][0];
            #pragma unroll
            for (int k = 1; k < 16; k++) m = fmaxf(m, v[r][k]);
            mv[r] = m;
        }
        #pragma unroll
        for (int o = 16; o; o >>= 1) {
            #pragma unroll
            for (int r = 0; r < 4; r++)
                mv[r] = fmaxf(mv[r], __shfl_xor_sync(0xffffffffu, mv[r], o));
        }

        float tau[4];
        #pragma unroll
        for (int r = 0; r < 4; r++) tau[r] = mv[r] - 1.0f;

        #pragma unroll 1
        for (int it = 0; it < 64; it++) {
            float s[4];
            unsigned c[4];
            #pragma unroll
            for (int r = 0; r < 4; r++) {
                float sr = 0.f; unsigned cr = 0;
                #pragma unroll
                for (int k = 0; k < 16; k++) {
                    float d = v[r][k] - tau[r];
                    if (d > 0.f) { sr += d; cr++; }
                }
                s[r] = sr; c[r] = cr;
            }
            #pragma unroll
            for (int o = 16; o; o >>= 1) {
                #pragma unroll
                for (int r = 0; r < 4; r++)
                    s[r] += __shfl_xor_sync(0xffffffffu, s[r], o);
            }
            #pragma unroll
            for (int r = 0; r < 4; r++)
                c[r] = __reduce_add_sync(0xffffffffu, c[r]);

            bool any = false;
            #pragma unroll
            for (int r = 0; r < 4; r++) {
                float tn = tau[r] + (s[r] - 1.0f) / (float)c[r];
                if (tn > tau[r]) { tau[r] = tn; any = true; }
            }
            if (!any) break;   // all 4 rows converged (uniform across warp)
        }

        #pragma unroll
        for (int r = 0; r < 4; r++) {
            float4* rp = reinterpret_cast<float4*>(out + (size_t)(rbase + r) * D_OUT);
            #pragma unroll
            for (int j = 0; j < 4; j++) {
                float4 y;
                y.x = fmaxf(v[r][j * 4 + 0] - tau[r], 0.f);
                y.y = fmaxf(v[r][j * 4 + 1] - tau[r], 0.f);
                y.z = fmaxf(v[r][j * 4 + 2] - tau[r], 0.f);
                y.w = fmaxf(v[r][j * 4 + 3] - tau[r], 0.f);
                rp[j * 32 + lane] = y;
            }
        }
    }
}

// ============================================================================
extern "C" void kernel_launch(void* const* d_in, const int* in_sizes, int n_in,
                              void* d_out, int out_size)
{
    (void)in_sizes; (void)n_in; (void)out_size;
    const float* priors = (const float*)d_in[0];
    const float* feat   = (const float*)d_in[1];
    const float* W      = (const float*)d_in[2];
    const float* gamma  = (const float*)d_in[3];
    const float* beta   = (const float*)d_in[4];
    float* out = (float*)d_out;

    prep_w<<<32, 256>>>(W);
    cudaFuncSetAttribute(fused_attentive, cudaFuncAttributeMaxDynamicSharedMemorySize, SM_TOT);
    fused_attentive<<<N_B / VBS, 512, SM_TOT>>>(out, priors, feat, gamma, beta);
}

// round 16
// speedup vs baseline: 1.1772x; 1.1772x over previous
#include <cuda_runtime.h>
#include <cuda_fp16.h>
#include <cstdint>

#define N_B    131072
#define D_IN   128
#define D_OUT  512
#define VBS    128
#define EPS_BN 1e-5f

// ---------------- SMEM layout (bytes) ----------------
#define SA      0           // A tile 32KB (128x128 fp16, 256B row stride, swizzled)
#define SW0     32768       // W tile buffer 0, 32KB
#define SW1     65536       // W tile buffer 1, 32KB
#define SSUM    98304       // 4 (mw) x 512 cols f32 partial sums
#define SSQ     106496      // 4 x 512 f32 partial sumsq
#define SAB_A   114688      // 512 f32 affine scale
#define SAB_B   116736      // 512 f32 affine shift
#define SM_TOT  118784

// W pre-converted to fp16, swizzled, chunk-tiled: 4 chunks x 32KB
__device__ __align__(16) unsigned char gWh[131072];

__device__ __forceinline__ uint32_t smem_u32(const void* p) {
    uint32_t a;
    asm("{ .reg .u64 t; cvta.to.shared.u64 t, %1; cvt.u32.u64 %0, t; }" : "=r"(a) : "l"(p));
    return a;
}
__device__ __forceinline__ void ldsm4(uint32_t* r, uint32_t addr) {
    asm volatile("ldmatrix.sync.aligned.m8n8.x4.shared.b16 {%0,%1,%2,%3}, [%4];"
                 : "=r"(r[0]), "=r"(r[1]), "=r"(r[2]), "=r"(r[3]) : "r"(addr));
}
__device__ __forceinline__ void mma16816(float* c, const uint32_t* a, const uint32_t* b) {
    asm volatile("mma.sync.aligned.m16n8k16.row.col.f32.f16.f16.f32 "
                 "{%0,%1,%2,%3}, {%4,%5,%6,%7}, {%8,%9}, {%0,%1,%2,%3};"
                 : "+f"(c[0]), "+f"(c[1]), "+f"(c[2]), "+f"(c[3])
                 : "r"(a[0]), "r"(a[1]), "r"(a[2]), "r"(a[3]), "r"(b[0]), "r"(b[1]));
}
__device__ __forceinline__ uint32_t pkh(float a, float b) {
    __half2 h = __floats2half2_rn(a, b);
    union { __half2 v; uint32_t u; } cv; cv.v = h;
    return cv.u;
}
__device__ __forceinline__ void cp16(uint32_t saddr, const void* g) {
    asm volatile("cp.async.cg.shared.global [%0], [%1], 16;" :: "r"(saddr), "l"(g) : "memory");
}
__device__ __forceinline__ void cp_commit() {
    asm volatile("cp.async.commit_group;" ::: "memory");
}

// ============================================================================
// Prep: W [512,128] f32 -> fp16, swizzled, chunk-tiled in gWh (once/launch).
// ============================================================================
__global__ __launch_bounds__(256) void prep_w(const float* __restrict__ W) {
    int idx = blockIdx.x * 256 + threadIdx.x;    // 0..8191 (16B chunks)
    int c = idx >> 11, j = idx & 2047;
    int row = j >> 4, ch = j & 15;
    const float4* gp = reinterpret_cast<const float4*>(W + ((size_t)(c * 128 + row) * 128 + ch * 8));
    float4 u = gp[0], v = gp[1];
    uint4 h4 = make_uint4(pkh(u.x, u.y), pkh(u.z, u.w),
                          pkh(v.x, v.y), pkh(v.z, v.w));
    *reinterpret_cast<uint4*>(gWh + c * 32768 + row * 256 + ((ch ^ (row & 7)) << 4)) = h4;
}

// ============================================================================
// Fused: fp16 mma GEMM (raw x -> out, L2-resident round trip, exact f32) +
// deferred GhostBN fold + sparsemax tail (2-row interleaved Newton, redux
// counts) applying (x*a+b)*prior in-register.
// grid = 1024 (one CTA per virtual batch of 128 rows), block = 512.
// ============================================================================
__global__ __launch_bounds__(512, 1) void fused_attentive(
    float* __restrict__ out, const float* __restrict__ priors,
    const float* __restrict__ feat,
    const float* __restrict__ gamma, const float* __restrict__ beta)
{
    extern __shared__ char smem[];
    const uint32_t sb = smem_u32(smem);
    const int tid = threadIdx.x;
    const int w = tid >> 5, lane = tid & 31;
    const int mw = w & 3, nw = w >> 2;           // warp grid 4(M) x 4(N)
    const int m0 = blockIdx.x * VBS;

    float* ssum = reinterpret_cast<float*>(smem + SSUM);
    float* ssq  = reinterpret_cast<float*>(smem + SSQ);
    float* aarr = reinterpret_cast<float*>(smem + SAB_A);
    float* barr = reinterpret_cast<float*>(smem + SAB_B);

    // ---- prefetch W chunks 0,1 via cp.async (pre-swizzled fp16: linear copy) ----
    #pragma unroll
    for (int i = 0; i < 4; i++) {
        int idx = tid + i * 512;
        cp16(sb + SW0 + idx * 16, gWh + idx * 16);
    }
    cp_commit();
    #pragma unroll
    for (int i = 0; i < 4; i++) {
        int idx = tid + i * 512;
        cp16(sb + SW1 + idx * 16, gWh + 32768 + idx * 16);
    }
    cp_commit();

    // ---- A tile (feat 128x128) — conversion overlaps W cp.async ----
    {
        const float* g = feat + (size_t)m0 * D_IN;
        #pragma unroll
        for (int i = 0; i < 4; i++) {
            int idx = tid + i * 512;             // 2048 16B chunk-slots
            int row = idx >> 4, ch = idx & 15;
            const float4* gp = reinterpret_cast<const float4*>(g + row * 128 + ch * 8);
            float4 u = gp[0], v = gp[1];
            uint4 h4 = make_uint4(pkh(u.x, u.y), pkh(u.z, u.w),
                                  pkh(v.x, v.y), pkh(v.z, v.w));
            uint32_t off = (uint32_t)(row * 256 + ((ch ^ (row & 7)) << 4));
            *reinterpret_cast<uint4*>(smem + SA + off) = h4;
        }
    }

    // per-lane ldmatrix address components
    const int a_row = mw * 32 + (((lane >> 3) & 1) << 3) + (lane & 7);
    const int a_sel = lane >> 4;
    const int b_row = nw * 32 + ((lane >> 4) << 3) + (lane & 7);
    const int b_sel = (lane >> 3) & 1;
    const int a_m7 = a_row & 7, b_m7 = b_row & 7;

    #pragma unroll 1
    for (int chunk = 0; chunk < 4; chunk++) {
        if (chunk < 3) asm volatile("cp.async.wait_group 1;" ::: "memory");
        else           asm volatile("cp.async.wait_group 0;" ::: "memory");
        __syncthreads();
        const uint32_t swb = (chunk & 1) ? (sb + SW1) : (sb + SW0);

        // ---- GEMM: warp tile 32(M) x 32(N) ----
        float acc[2][4][4];
        #pragma unroll
        for (int mt = 0; mt < 2; mt++)
            #pragma unroll
            for (int nt = 0; nt < 4; nt++)
                #pragma unroll
                for (int q = 0; q < 4; q++) acc[mt][nt][q] = 0.0f;

        #pragma unroll
        for (int s = 0; s < 8; s++) {
            uint32_t aF[2][4], bF[2][4];
            #pragma unroll
            for (int mt = 0; mt < 2; mt++) {
                uint32_t off = (uint32_t)((a_row + mt * 16) * 256 +
                               (((2 * s + a_sel) ^ a_m7) << 4));
                ldsm4(aF[mt], sb + SA + off);
            }
            #pragma unroll
            for (int np = 0; np < 2; np++) {
                uint32_t off = (uint32_t)((b_row + np * 16) * 256 +
                               (((2 * s + b_sel) ^ b_m7) << 4));
                ldsm4(bF[np], swb + off);
            }
            #pragma unroll
            for (int mt = 0; mt < 2; mt++)
                #pragma unroll
                for (int nt = 0; nt < 4; nt++)
                    mma16816(acc[mt][nt], aF[mt], &bF[nt >> 1][(nt & 1) * 2]);
        }

        // ---- store raw x to out (L2-resident round trip, exact f32) ----
        #pragma unroll
        for (int nt = 0; nt < 4; nt++) {
            int gcol = chunk * 128 + nw * 32 + nt * 8 + 2 * (lane & 3);
            #pragma unroll
            for (int mt = 0; mt < 2; mt++) {
                int r0 = m0 + mw * 32 + mt * 16 + (lane >> 2);
                *reinterpret_cast<float2*>(out + (size_t)r0 * D_OUT + gcol) =
                    make_float2(acc[mt][nt][0], acc[mt][nt][1]);
                *reinterpret_cast<float2*>(out + (size_t)(r0 + 8) * D_OUT + gcol) =
                    make_float2(acc[mt][nt][2], acc[mt][nt][3]);
            }
        }

        // ---- column stats (race-free slots: (mw, global col) unique; no sync) ----
        #pragma unroll
        for (int nt = 0; nt < 4; nt++) {
            float s0 = 0.f, s1 = 0.f, q0 = 0.f, q1 = 0.f;
            #pragma unroll
            for (int mt = 0; mt < 2; mt++) {
                float c0 = acc[mt][nt][0], c1 = acc[mt][nt][1];
                float c2 = acc[mt][nt][2], c3 = acc[mt][nt][3];
                s0 += c0 + c2;  s1 += c1 + c3;
                q0 += c0 * c0 + c2 * c2;  q1 += c1 * c1 + c3 * c3;
            }
            #pragma unroll
            for (int o = 4; o < 32; o <<= 1) {
                s0 += __shfl_xor_sync(0xffffffffu, s0, o);
                s1 += __shfl_xor_sync(0xffffffffu, s1, o);
                q0 += __shfl_xor_sync(0xffffffffu, q0, o);
                q1 += __shfl_xor_sync(0xffffffffu, q1, o);
            }
            if (lane < 4) {
                int gcol = chunk * 128 + nw * 32 + nt * 8 + 2 * lane;
                ssum[mw * 512 + gcol]     = s0;  ssum[mw * 512 + gcol + 1] = s1;
                ssq [mw * 512 + gcol]     = q0;  ssq [mw * 512 + gcol + 1] = q1;
            }
        }
        __syncthreads();   // MMA reads of swb done -> safe to prefetch into it

        if (chunk + 2 < 4) {
            const unsigned char* src = gWh + (chunk + 2) * 32768;
            #pragma unroll
            for (int i = 0; i < 4; i++) {
                int idx = tid + i * 512;
                cp16(swb + idx * 16, src + idx * 16);
            }
            cp_commit();
        }
    }

    // ---- fold BN into per-col affine (once, deterministic combine) ----
    {
        int c = tid;                               // 512 threads = 512 cols
        float s = ssum[c] + ssum[512 + c] + ssum[1024 + c] + ssum[1536 + c];
        float q = ssq[c]  + ssq[512 + c]  + ssq[1024 + c]  + ssq[1536 + c];
        float mean = s * (1.0f / VBS);
        float var  = q * (1.0f / VBS) - mean * mean;
        float av = gamma[c] * rsqrtf(var + EPS_BN);
        aarr[c] = av;
        barr[c] = beta[c] - mean * av;
    }
    __syncthreads();

    // ======================= fused sparsemax tail ===========================
    // Warp handles 8 rows, 2 at a time (interleaved Newton chains; support
    // counts via redux.sync). x re-read is an L2 hit (written above by this
    // CTA); y=(x*a+b)*prior formed in-register. Monotone Newton from
    // t0=max-1 is the exact fixed point of the piecewise-linear sparsemax
    // equation.
    #pragma unroll 1
    for (int rr = 0; rr < 4; rr++) {
        const int row0 = m0 + w * 8 + rr;
        const int row1 = row0 + 4;
        float4* rp0 = reinterpret_cast<float4*>(out + (size_t)row0 * D_OUT);
        float4* rp1 = reinterpret_cast<float4*>(out + (size_t)row1 * D_OUT);
        const float4* pp0 = reinterpret_cast<const float4*>(priors + (size_t)row0 * D_OUT);
        const float4* pp1 = reinterpret_cast<const float4*>(priors + (size_t)row1 * D_OUT);

        float4 v0[4], v1[4];
        #pragma unroll
        for (int j = 0; j < 4; j++) {
            float4 a4 = *reinterpret_cast<const float4*>(aarr + j * 128 + lane * 4);
            float4 b4 = *reinterpret_cast<const float4*>(barr + j * 128 + lane * 4);
            float4 x0 = rp0[j * 32 + lane], p0 = pp0[j * 32 + lane];
            float4 x1 = rp1[j * 32 + lane], p1 = pp1[j * 32 + lane];
            v0[j].x = fmaf(x0.x, a4.x, b4.x) * p0.x;
            v0[j].y = fmaf(x0.y, a4.y, b4.y) * p0.y;
            v0[j].z = fmaf(x0.z, a4.z, b4.z) * p0.z;
            v0[j].w = fmaf(x0.w, a4.w, b4.w) * p0.w;
            v1[j].x = fmaf(x1.x, a4.x, b4.x) * p1.x;
            v1[j].y = fmaf(x1.y, a4.y, b4.y) * p1.y;
            v1[j].z = fmaf(x1.z, a4.z, b4.z) * p1.z;
            v1[j].w = fmaf(x1.w, a4.w, b4.w) * p1.w;
        }

        float m0v = v0[0].x, m1v = v1[0].x;
        #pragma unroll
        for (int j = 0; j < 4; j++) {
            m0v = fmaxf(m0v, fmaxf(fmaxf(v0[j].x, v0[j].y), fmaxf(v0[j].z, v0[j].w)));
            m1v = fmaxf(m1v, fmaxf(fmaxf(v1[j].x, v1[j].y), fmaxf(v1[j].z, v1[j].w)));
        }
        #pragma unroll
        for (int o = 16; o; o >>= 1) {
            m0v = fmaxf(m0v, __shfl_xor_sync(0xffffffffu, m0v, o));
            m1v = fmaxf(m1v, __shfl_xor_sync(0xffffffffu, m1v, o));
        }

        float tau0 = m0v - 1.0f, tau1 = m1v - 1.0f;
        #pragma unroll 1
        for (int it = 0; it < 64; it++) {
            float s0 = 0.f, s1 = 0.f;
            unsigned c0 = 0, c1 = 0;
            #pragma unroll
            for (int j = 0; j < 4; j++) {
                float d;
                d = v0[j].x - tau0; if (d > 0.f) { s0 += d; c0++; }
                d = v0[j].y - tau0; if (d > 0.f) { s0 += d; c0++; }
                d = v0[j].z - tau0; if (d > 0.f) { s0 += d; c0++; }
                d = v0[j].w - tau0; if (d > 0.f) { s0 += d; c0++; }
                d = v1[j].x - tau1; if (d > 0.f) { s1 += d; c1++; }
                d = v1[j].y - tau1; if (d > 0.f) { s1 += d; c1++; }
                d = v1[j].z - tau1; if (d > 0.f) { s1 += d; c1++; }
                d = v1[j].w - tau1; if (d > 0.f) { s1 += d; c1++; }
            }
            #pragma unroll
            for (int o = 16; o; o >>= 1) {
                s0 += __shfl_xor_sync(0xffffffffu, s0, o);
                s1 += __shfl_xor_sync(0xffffffffu, s1, o);
            }
            c0 = __reduce_add_sync(0xffffffffu, c0);
            c1 = __reduce_add_sync(0xffffffffu, c1);

            float tn0 = tau0 + (s0 - 1.0f) / (float)c0;
            float tn1 = tau1 + (s1 - 1.0f) / (float)c1;
            bool a0 = tn0 > tau0, a1 = tn1 > tau1;
            if (a0) tau0 = tn0;
            if (a1) tau1 = tn1;
            if (!a0 && !a1) break;   // both converged (uniform across warp)
        }

        #pragma unroll
        for (int j = 0; j < 4; j++) {
            float4 y0, y1;
            y0.x = fmaxf(v0[j].x - tau0, 0.f);  y0.y = fmaxf(v0[j].y - tau0, 0.f);
            y0.z = fmaxf(v0[j].z - tau0, 0.f);  y0.w = fmaxf(v0[j].w - tau0, 0.f);
            y1.x = fmaxf(v1[j].x - tau1, 0.f);  y1.y = fmaxf(v1[j].y - tau1, 0.f);
            y1.z = fmaxf(v1[j].z - tau1, 0.f);  y1.w = fmaxf(v1[j].w - tau1, 0.f);
            rp0[j * 32 + lane] = y0;
            rp1[j * 32 + lane] = y1;
        }
    }
}

// ============================================================================
extern "C" void kernel_launch(void* const* d_in, const int* in_sizes, int n_in,
                              void* d_out, int out_size)
{
    (void)in_sizes; (void)n_in; (void)out_size;
    const float* priors = (const float*)d_in[0];
    const float* feat   = (const float*)d_in[1];
    const float* W      = (const float*)d_in[2];
    const float* gamma  = (const float*)d_in[3];
    const float* beta   = (const float*)d_in[4];
    float* out = (float*)d_out;

    prep_w<<<32, 256>>>(W);
    cudaFuncSetAttribute(fused_attentive, cudaFuncAttributeMaxDynamicSharedMemorySize, SM_TOT);
    fused_attentive<<<N_B / VBS, 512, SM_TOT>>>(out, priors, feat, gamma, beta);
}